// round 1
// baseline (speedup 1.0000x reference)
#include <cuda_runtime.h>

#define NN   100000
#define EE   1600000
#define EAA  1000000
#define GG   512
#define F_INN 16
#define HH   32

// ---- scratch (device globals: no allocation allowed) ----
__device__ __align__(16) float g_deg[NN];        // deg, then dinv (in place)
__device__ __align__(16) float g_xw [NN * HH];   // x@W (per layer)
__device__ __align__(16) float g_agg[NN * HH];   // scatter accumulator
__device__ __align__(16) float g_h  [NN * HH];   // layer output
__device__ __align__(16) float g_u  [NN * HH];   // h @ Wbil (bilinear precompute)
__device__ __align__(16) float g_pooled[GG * HH];
__device__ float g_cnt[GG];

// ---------------- kernels ----------------

__global__ void k_init() {
    int idx = blockIdx.x * blockDim.x + threadIdx.x;
    if (idx < NN * HH) g_agg[idx] = 0.f;
    if (idx < NN)      g_deg[idx] = 1.0f;          // self-loop
    if (idx < GG * HH) g_pooled[idx] = 0.f;
    if (idx < GG)      g_cnt[idx] = 0.f;
}

__global__ void k_deg(const int* __restrict__ dst) {
    int e = blockIdx.x * blockDim.x + threadIdx.x;
    if (e < EE) atomicAdd(&g_deg[dst[e]], 1.0f);
}

__global__ void k_dinv() {
    int i = blockIdx.x * blockDim.x + threadIdx.x;
    if (i < NN) g_deg[i] = rsqrtf(g_deg[i]);
}

// xw = x @ W1   (x: [N,16], W1: [16,32]) ; one thread per output element
__global__ void k_xw1(const float* __restrict__ x, const float* __restrict__ W1) {
    __shared__ float sW[F_INN * HH];
    for (int i = threadIdx.x; i < F_INN * HH; i += blockDim.x) sW[i] = W1[i];
    __syncthreads();
    int idx = blockIdx.x * blockDim.x + threadIdx.x;
    if (idx >= NN * HH) return;
    int node = idx >> 5, h = idx & 31;
    const float* xr = x + node * F_INN;
    float acc = 0.f;
#pragma unroll
    for (int k = 0; k < F_INN; k++) acc = fmaf(xr[k], sW[k * HH + h], acc);
    g_xw[idx] = acc;
}

// out = g_h @ W  (W: [32,32]); out_is_u ? g_u : g_xw
__global__ void k_mm32(const float* __restrict__ W, int out_is_u) {
    __shared__ float sW[HH * HH];
    for (int i = threadIdx.x; i < HH * HH; i += blockDim.x) sW[i] = W[i];
    __syncthreads();
    int idx = blockIdx.x * blockDim.x + threadIdx.x;
    if (idx >= NN * HH) return;
    int node = idx >> 5, h = idx & 31;
    const float* hr = g_h + node * HH;
    float acc = 0.f;
#pragma unroll
    for (int k = 0; k < HH; k++) acc = fmaf(hr[k], sW[k * HH + h], acc);
    float* out = out_is_u ? g_u : g_xw;
    out[idx] = acc;
}

// edge scatter: agg[dst] += xw[src] * dinv[src]*dinv[dst]
// 8 threads per edge, float4 HW atomics (sm_90+)
__global__ void k_scatter(const int* __restrict__ src, const int* __restrict__ dst) {
    int t = blockIdx.x * blockDim.x + threadIdx.x;
    if (t >= EE * 8) return;
    int e = t >> 3, c = t & 7;
    int s = src[e], d = dst[e];
    float coef = g_deg[s] * g_deg[d];          // dinv values
    float4 v = reinterpret_cast<const float4*>(g_xw)[s * 8 + c];
    v.x *= coef; v.y *= coef; v.z *= coef; v.w *= coef;
    atomicAdd(reinterpret_cast<float4*>(g_agg) + d * 8 + c, v);
}

// layer-1 epilogue: h = relu(agg + xw*dinv^2 + b1); reset agg
__global__ void k_finish1(const float* __restrict__ b1) {
    int idx = blockIdx.x * blockDim.x + threadIdx.x;
    if (idx >= NN * HH) return;
    int node = idx >> 5, h = idx & 31;
    float dv = g_deg[node];
    float v = g_agg[idx] + g_xw[idx] * dv * dv + b1[h];
    g_h[idx] = v > 0.f ? v : 0.f;
    g_agg[idx] = 0.f;
}

// layer-2 epilogue: h = agg + xw*dinv^2 + b2; fused mean-pool accumulation
__global__ void k_finish2(const float* __restrict__ b2, const int* __restrict__ batch) {
    int idx = blockIdx.x * blockDim.x + threadIdx.x;
    if (idx >= NN * HH) return;
    int node = idx >> 5, h = idx & 31;
    float dv = g_deg[node];
    float v = g_agg[idx] + g_xw[idx] * dv * dv + b2[h];
    g_h[idx] = v;
    int g = batch[node];
    atomicAdd(&g_pooled[g * HH + h], v);
    if (h == 0) atomicAdd(&g_cnt[g], 1.0f);
}

// reg_output[g] = (pooled[g]/max(cnt,1)) @ Wr + br
__global__ void k_reg(const float* __restrict__ Wr, const float* __restrict__ br,
                      float* __restrict__ out) {
    int g = blockIdx.x * blockDim.x + threadIdx.x;
    if (g >= GG) return;
    float c = g_cnt[g];
    c = c < 1.f ? 1.f : c;
    float acc = 0.f;
#pragma unroll
    for (int h = 0; h < HH; h++) acc = fmaf(g_pooled[g * HH + h], Wr[h], acc);
    out[g] = acc / c + br[0];
}

// edge_pred[e] = dot(u[src_e], h[dst_e]) + bbil   (warp per edge)
__global__ void k_edge(const int* __restrict__ asrc, const int* __restrict__ adst,
                       const float* __restrict__ bbil, float* __restrict__ out) {
    int t = blockIdx.x * blockDim.x + threadIdx.x;
    int e = t >> 5, lane = t & 31;
    if (e >= EAA) return;
    float a = g_u[asrc[e] * HH + lane];
    float b = g_h[adst[e] * HH + lane];
    float p = a * b;
#pragma unroll
    for (int off = 16; off; off >>= 1) p += __shfl_down_sync(0xffffffffu, p, off);
    if (lane == 0) out[GG + e] = p + bbil[0];
}

// ---------------- launch ----------------

extern "C" void kernel_launch(void* const* d_in, const int* in_sizes, int n_in,
                              void* d_out, int out_size) {
    const float* x    = (const float*)d_in[0];
    const int*   ei   = (const int*)  d_in[1];
    const int*   eia  = (const int*)  d_in[2];
    const int*   batch= (const int*)  d_in[3];
    const float* W1   = (const float*)d_in[4];
    const float* b1   = (const float*)d_in[5];
    const float* W2   = (const float*)d_in[6];
    const float* b2   = (const float*)d_in[7];
    const float* Wr   = (const float*)d_in[8];
    const float* br   = (const float*)d_in[9];
    const float* Wbil = (const float*)d_in[10];
    const float* bbil = (const float*)d_in[11];
    float* out = (float*)d_out;

    const int* src  = ei;
    const int* dst  = ei + EE;
    const int* asrc = eia;
    const int* adst = eia + EAA;

    const int B = 256;
    const int NH = NN * HH;

    k_init   <<<(NH + B - 1) / B, B>>>();
    k_deg    <<<(EE + B - 1) / B, B>>>(dst);
    k_dinv   <<<(NN + B - 1) / B, B>>>();

    // layer 1
    k_xw1    <<<(NH + B - 1) / B, B>>>(x, W1);
    k_scatter<<<(EE * 8 + B - 1) / B, B>>>(src, dst);
    k_finish1<<<(NH + B - 1) / B, B>>>(b1);

    // layer 2 (+ fused pooling)
    k_mm32   <<<(NH + B - 1) / B, B>>>(W2, 0);
    k_scatter<<<(EE * 8 + B - 1) / B, B>>>(src, dst);
    k_finish2<<<(NH + B - 1) / B, B>>>(b2, batch);

    // heads
    k_reg    <<<(GG + B - 1) / B, B>>>(Wr, br, out);
    k_mm32   <<<(NH + B - 1) / B, B>>>(Wbil, 1);      // u = h @ Wbil
    k_edge   <<<((long)EAA * 32 + B - 1) / B, B>>>(asrc, adst, bbil, out);
}

// round 2
// speedup vs baseline: 1.6470x; 1.6470x over previous
#include <cuda_runtime.h>

#define NN   100000
#define EE   1600000
#define EAA  1000000
#define GG   512
#define F_INN 16
#define HH   32

// ---- scratch (device globals) ----
__device__ __align__(16) float g_deg[NN];        // deg -> dinv (in place)
__device__ __align__(16) float g_y  [NN * HH];   // y = (x@W)*dinv  (scatter source)
__device__ __align__(16) float g_agg[NN * HH];   // accumulator, seeded with y (self loop)
__device__ __align__(16) float g_h  [NN * HH];   // layer output
__device__ __align__(16) float g_u  [NN * HH];   // h @ Wbil
__device__ __align__(16) float g_pooled[GG * HH];
__device__ float g_cnt[GG];

// ---------------- kernels ----------------

__global__ void k_init() {
    int i = blockIdx.x * blockDim.x + threadIdx.x;
    if (i < NN)      g_deg[i] = 1.0f;            // self-loop
    if (i < GG * HH) g_pooled[i] = 0.f;
    if (i < GG)      g_cnt[i] = 0.f;
}

__global__ void k_deg(const int* __restrict__ dst) {
    int e = blockIdx.x * blockDim.x + threadIdx.x;
    if (e < EE) atomicAdd(&g_deg[dst[e]], 1.0f);
}

__global__ void k_dinv() {
    int i = blockIdx.x * blockDim.x + threadIdx.x;
    if (i < NN) g_deg[i] = rsqrtf(g_deg[i]);
}

// y = (x @ W1) * dinv ; one THREAD per node; also seeds g_agg = y
__global__ void k_mm1(const float* __restrict__ x, const float* __restrict__ W1) {
    __shared__ float sW[F_INN * HH];
    for (int i = threadIdx.x; i < F_INN * HH; i += blockDim.x) sW[i] = W1[i];
    __syncthreads();
    int node = blockIdx.x * blockDim.x + threadIdx.x;
    if (node >= NN) return;
    float acc[HH];
#pragma unroll
    for (int j = 0; j < HH; j++) acc[j] = 0.f;
    const float4* xr = reinterpret_cast<const float4*>(x + node * F_INN);
#pragma unroll
    for (int kk = 0; kk < F_INN / 4; kk++) {
        float4 xv = xr[kk];
        float xs[4] = {xv.x, xv.y, xv.z, xv.w};
#pragma unroll
        for (int q = 0; q < 4; q++) {
            int k = kk * 4 + q;
#pragma unroll
            for (int j = 0; j < HH; j++) acc[j] = fmaf(xs[q], sW[k * HH + j], acc[j]);
        }
    }
    float dv = g_deg[node];
    float4* yo = reinterpret_cast<float4*>(g_y)   + node * 8;
    float4* ao = reinterpret_cast<float4*>(g_agg) + node * 8;
#pragma unroll
    for (int c = 0; c < 8; c++) {
        float4 v = make_float4(acc[4*c]*dv, acc[4*c+1]*dv, acc[4*c+2]*dv, acc[4*c+3]*dv);
        yo[c] = v; ao[c] = v;
    }
}

// generic 32x32: out = (g_h @ W) [* dinv] ; one thread per node
// mode 0: y&agg (with dinv), mode 1: u (no dinv, single write)
__global__ void k_mm32(const float* __restrict__ W, int mode) {
    __shared__ float sW[HH * HH];
    for (int i = threadIdx.x; i < HH * HH; i += blockDim.x) sW[i] = W[i];
    __syncthreads();
    int node = blockIdx.x * blockDim.x + threadIdx.x;
    if (node >= NN) return;
    float acc[HH];
#pragma unroll
    for (int j = 0; j < HH; j++) acc[j] = 0.f;
    const float4* hr = reinterpret_cast<const float4*>(g_h + node * HH);
#pragma unroll
    for (int kk = 0; kk < HH / 4; kk++) {
        float4 hv = hr[kk];
        float hs[4] = {hv.x, hv.y, hv.z, hv.w};
#pragma unroll
        for (int q = 0; q < 4; q++) {
            int k = kk * 4 + q;
#pragma unroll
            for (int j = 0; j < HH; j++) acc[j] = fmaf(hs[q], sW[k * HH + j], acc[j]);
        }
    }
    if (mode == 0) {
        float dv = g_deg[node];
        float4* yo = reinterpret_cast<float4*>(g_y)   + node * 8;
        float4* ao = reinterpret_cast<float4*>(g_agg) + node * 8;
#pragma unroll
        for (int c = 0; c < 8; c++) {
            float4 v = make_float4(acc[4*c]*dv, acc[4*c+1]*dv, acc[4*c+2]*dv, acc[4*c+3]*dv);
            yo[c] = v; ao[c] = v;
        }
    } else {
        float4* uo = reinterpret_cast<float4*>(g_u) + node * 8;
#pragma unroll
        for (int c = 0; c < 8; c++)
            uo[c] = make_float4(acc[4*c], acc[4*c+1], acc[4*c+2], acc[4*c+3]);
    }
}

// edge scatter: agg[dst] += y[src]   (8 threads/edge, float4 HW RED)
__global__ void k_scatter(const int* __restrict__ src, const int* __restrict__ dst) {
    long t = (long)blockIdx.x * blockDim.x + threadIdx.x;
    if (t >= (long)EE * 8) return;
    int e = (int)(t >> 3), c = (int)(t & 7);
    int s = src[e], d = dst[e];
    float4 v = reinterpret_cast<const float4*>(g_y)[s * 8 + c];
    atomicAdd(reinterpret_cast<float4*>(g_agg) + d * 8 + c, v);
}

// layer-1 epilogue: h = relu(agg*dinv + b1)   (float4)
__global__ void k_finish1(const float* __restrict__ b1) {
    int t = blockIdx.x * blockDim.x + threadIdx.x;
    if (t >= NN * 8) return;
    int node = t >> 3, c = t & 7;
    float dv = g_deg[node];
    float4 bv = reinterpret_cast<const float4*>(b1)[c];
    float4 a = reinterpret_cast<const float4*>(g_agg)[t];
    float4 v;
    v.x = fmaxf(a.x * dv + bv.x, 0.f);
    v.y = fmaxf(a.y * dv + bv.y, 0.f);
    v.z = fmaxf(a.z * dv + bv.z, 0.f);
    v.w = fmaxf(a.w * dv + bv.w, 0.f);
    reinterpret_cast<float4*>(g_h)[t] = v;
}

// layer-2 epilogue: h = agg*dinv + b2 ; fused mean-pool accumulation (float4 atomics)
__global__ void k_finish2(const float* __restrict__ b2, const int* __restrict__ batch) {
    int t = blockIdx.x * blockDim.x + threadIdx.x;
    if (t >= NN * 8) return;
    int node = t >> 3, c = t & 7;
    float dv = g_deg[node];
    float4 bv = reinterpret_cast<const float4*>(b2)[c];
    float4 a = reinterpret_cast<const float4*>(g_agg)[t];
    float4 v;
    v.x = a.x * dv + bv.x;
    v.y = a.y * dv + bv.y;
    v.z = a.z * dv + bv.z;
    v.w = a.w * dv + bv.w;
    reinterpret_cast<float4*>(g_h)[t] = v;
    int g = batch[node];
    atomicAdd(reinterpret_cast<float4*>(g_pooled) + g * 8 + c, v);
    if (c == 0) atomicAdd(&g_cnt[g], 1.0f);
}

// reg_output[g] = (pooled[g]/max(cnt,1)) @ Wr + br
__global__ void k_reg(const float* __restrict__ Wr, const float* __restrict__ br,
                      float* __restrict__ out) {
    int g = blockIdx.x * blockDim.x + threadIdx.x;
    if (g >= GG) return;
    float c = g_cnt[g];
    c = c < 1.f ? 1.f : c;
    float acc = 0.f;
#pragma unroll
    for (int h = 0; h < HH; h++) acc = fmaf(g_pooled[g * HH + h], Wr[h], acc);
    out[g] = acc / c + br[0];
}

// edge_pred[e] = dot(u[src_e], h[dst_e]) + bbil   (8 threads/edge, float4)
__global__ void k_edge(const int* __restrict__ asrc, const int* __restrict__ adst,
                       const float* __restrict__ bbil, float* __restrict__ out) {
    long t = (long)blockIdx.x * blockDim.x + threadIdx.x;
    int e = (int)(t >> 3), lane = (int)(t & 7);
    if (e >= EAA) return;
    float4 a = reinterpret_cast<const float4*>(g_u)[asrc[e] * 8 + lane];
    float4 b = reinterpret_cast<const float4*>(g_h)[adst[e] * 8 + lane];
    float p = a.x * b.x + a.y * b.y + a.z * b.z + a.w * b.w;
#pragma unroll
    for (int off = 4; off; off >>= 1) p += __shfl_down_sync(0xffffffffu, p, off, 8);
    if (lane == 0) out[GG + e] = p + bbil[0];
}

// ---------------- launch ----------------

extern "C" void kernel_launch(void* const* d_in, const int* in_sizes, int n_in,
                              void* d_out, int out_size) {
    const float* x    = (const float*)d_in[0];
    const int*   ei   = (const int*)  d_in[1];
    const int*   eia  = (const int*)  d_in[2];
    const int*   batch= (const int*)  d_in[3];
    const float* W1   = (const float*)d_in[4];
    const float* b1   = (const float*)d_in[5];
    const float* W2   = (const float*)d_in[6];
    const float* b2   = (const float*)d_in[7];
    const float* Wr   = (const float*)d_in[8];
    const float* br   = (const float*)d_in[9];
    const float* Wbil = (const float*)d_in[10];
    const float* bbil = (const float*)d_in[11];
    float* out = (float*)d_out;

    const int* src  = ei;
    const int* dst  = ei + EE;
    const int* asrc = eia;
    const int* adst = eia + EAA;

    const int B = 256;

    k_init  <<<(NN + B - 1) / B, B>>>();
    k_deg   <<<(EE + B - 1) / B, B>>>(dst);
    k_dinv  <<<(NN + B - 1) / B, B>>>();

    // layer 1
    k_mm1    <<<(NN + B - 1) / B, B>>>(x, W1);
    k_scatter<<<(int)(((long)EE * 8 + B - 1) / B), B>>>(src, dst);
    k_finish1<<<(NN * 8 + B - 1) / B, B>>>(b1);

    // layer 2 (+ fused pooling)
    k_mm32   <<<(NN + B - 1) / B, B>>>(W2, 0);
    k_scatter<<<(int)(((long)EE * 8 + B - 1) / B), B>>>(src, dst);
    k_finish2<<<(NN * 8 + B - 1) / B, B>>>(b2, batch);

    // heads
    k_reg    <<<(GG + B - 1) / B, B>>>(Wr, br, out);
    k_mm32   <<<(NN + B - 1) / B, B>>>(Wbil, 1);     // u = h @ Wbil
    k_edge   <<<(int)(((long)EAA * 8 + B - 1) / B), B>>>(asrc, adst, bbil, out);
}

// round 3
// speedup vs baseline: 1.6813x; 1.0208x over previous
#include <cuda_runtime.h>

#define NN   100000
#define EE   1600000
#define EAA  1000000
#define GG   512
#define F_INN 16
#define HH   32

// ---- scratch (device globals) ----
__device__ __align__(16) float g_deg[NN];        // deg -> dinv (in place)
__device__ __align__(16) float g_y  [NN * HH];   // scatter source
__device__ __align__(16) float g_agg[NN * HH];   // accumulator (seeded with self-loop term)
__device__ __align__(16) float g_h  [NN * HH];   // layer-2 output (for edge head)
__device__ __align__(16) float g_u  [NN * HH];   // h @ Wbil
__device__ __align__(16) float g_pooled[GG * HH];
__device__ float g_cnt[GG];

// ---------------- kernels ----------------

__global__ void k_init() {
    int i = blockIdx.x * blockDim.x + threadIdx.x;
    if (i < NN)      g_deg[i] = 1.0f;            // self-loop
    if (i < GG * HH) g_pooled[i] = 0.f;
    if (i < GG)      g_cnt[i] = 0.f;
}

__global__ void k_deg(const int* __restrict__ dst) {
    int e = blockIdx.x * blockDim.x + threadIdx.x;
    if (e < EE) atomicAdd(&g_deg[dst[e]], 1.0f);
}

__global__ void k_dinv() {
    int i = blockIdx.x * blockDim.x + threadIdx.x;
    if (i < NN) g_deg[i] = rsqrtf(g_deg[i]);
}

// y = (x @ W1) * dinv ; 4 threads per node, 8 output cols each; seeds g_agg = y
__global__ void k_mm1(const float* __restrict__ x, const float* __restrict__ W1) {
    __shared__ float sW[F_INN * HH];
    for (int i = threadIdx.x; i < F_INN * HH; i += blockDim.x) sW[i] = W1[i];
    __syncthreads();
    int t = blockIdx.x * blockDim.x + threadIdx.x;
    int node = t >> 2, q = t & 3;                 // cols [8q, 8q+8)
    if (node >= NN) return;
    float acc[8];
#pragma unroll
    for (int j = 0; j < 8; j++) acc[j] = 0.f;
    const float4* xr = reinterpret_cast<const float4*>(x + node * F_INN);
#pragma unroll
    for (int kk = 0; kk < F_INN / 4; kk++) {
        float4 xv = xr[kk];
        float xs[4] = {xv.x, xv.y, xv.z, xv.w};
#pragma unroll
        for (int p = 0; p < 4; p++) {
            int k = kk * 4 + p;
#pragma unroll
            for (int j = 0; j < 8; j++)
                acc[j] = fmaf(xs[p], sW[k * HH + q * 8 + j], acc[j]);
        }
    }
    float dv = g_deg[node];
    float4 v0 = make_float4(acc[0]*dv, acc[1]*dv, acc[2]*dv, acc[3]*dv);
    float4 v1 = make_float4(acc[4]*dv, acc[5]*dv, acc[6]*dv, acc[7]*dv);
    int o = node * 8 + q * 2;
    reinterpret_cast<float4*>(g_y)[o]     = v0;
    reinterpret_cast<float4*>(g_y)[o + 1] = v1;
    reinterpret_cast<float4*>(g_agg)[o]     = v0;
    reinterpret_cast<float4*>(g_agg)[o + 1] = v1;
}

// fused layer-1 epilogue + layer-2 matmul:
//   h1 = relu(agg*dinv + b1)  (in registers, never stored)
//   y2 = (h1 @ W2) * dinv ; writes g_y and seeds g_agg
// 4 threads per node (each computes 8 cols of y2; all load the full h1 row)
__global__ void k_layer2(const float* __restrict__ b1, const float* __restrict__ W2) {
    __shared__ float sW[HH * HH];
    __shared__ float sb[HH];
    for (int i = threadIdx.x; i < HH * HH; i += blockDim.x) sW[i] = W2[i];
    if (threadIdx.x < HH) sb[threadIdx.x] = b1[threadIdx.x];
    __syncthreads();
    int t = blockIdx.x * blockDim.x + threadIdx.x;
    int node = t >> 2, q = t & 3;
    if (node >= NN) return;
    float dv = g_deg[node];
    float h[HH];
    const float4* ar = reinterpret_cast<const float4*>(g_agg) + node * 8;
#pragma unroll
    for (int c = 0; c < 8; c++) {
        float4 a = ar[c];
        h[4*c+0] = fmaxf(a.x * dv + sb[4*c+0], 0.f);
        h[4*c+1] = fmaxf(a.y * dv + sb[4*c+1], 0.f);
        h[4*c+2] = fmaxf(a.z * dv + sb[4*c+2], 0.f);
        h[4*c+3] = fmaxf(a.w * dv + sb[4*c+3], 0.f);
    }
    float acc[8];
#pragma unroll
    for (int j = 0; j < 8; j++) acc[j] = 0.f;
#pragma unroll
    for (int k = 0; k < HH; k++) {
#pragma unroll
        for (int j = 0; j < 8; j++)
            acc[j] = fmaf(h[k], sW[k * HH + q * 8 + j], acc[j]);
    }
    float4 v0 = make_float4(acc[0]*dv, acc[1]*dv, acc[2]*dv, acc[3]*dv);
    float4 v1 = make_float4(acc[4]*dv, acc[5]*dv, acc[6]*dv, acc[7]*dv);
    int o = node * 8 + q * 2;
    reinterpret_cast<float4*>(g_y)[o]     = v0;
    reinterpret_cast<float4*>(g_y)[o + 1] = v1;
    reinterpret_cast<float4*>(g_agg)[o]     = v0;
    reinterpret_cast<float4*>(g_agg)[o + 1] = v1;
}

// edge scatter: agg[dst] += y[src]   (8 threads/edge, float4 HW RED)
__global__ void k_scatter(const int* __restrict__ src, const int* __restrict__ dst) {
    long t = (long)blockIdx.x * blockDim.x + threadIdx.x;
    if (t >= (long)EE * 8) return;
    int e = (int)(t >> 3), c = (int)(t & 7);
    int s = src[e], d = dst[e];
    float4 v = reinterpret_cast<const float4*>(g_y)[s * 8 + c];
    atomicAdd(reinterpret_cast<float4*>(g_agg) + d * 8 + c, v);
}

// fused layer-2 epilogue + mean-pool accumulation + bilinear precompute:
//   h2 = agg*dinv + b2 -> g_h ; pooled[batch] += h2 ; u = h2 @ Wbil -> g_u
// 4 threads per node
__global__ void k_head(const float* __restrict__ b2, const float* __restrict__ Wbil,
                       const int* __restrict__ batch) {
    __shared__ float sW[HH * HH];
    __shared__ float sb[HH];
    for (int i = threadIdx.x; i < HH * HH; i += blockDim.x) sW[i] = Wbil[i];
    if (threadIdx.x < HH) sb[threadIdx.x] = b2[threadIdx.x];
    __syncthreads();
    int t = blockIdx.x * blockDim.x + threadIdx.x;
    int node = t >> 2, q = t & 3;
    if (node >= NN) return;
    float dv = g_deg[node];
    float h[HH];
    const float4* ar = reinterpret_cast<const float4*>(g_agg) + node * 8;
#pragma unroll
    for (int c = 0; c < 8; c++) {
        float4 a = ar[c];
        h[4*c+0] = a.x * dv + sb[4*c+0];
        h[4*c+1] = a.y * dv + sb[4*c+1];
        h[4*c+2] = a.z * dv + sb[4*c+2];
        h[4*c+3] = a.w * dv + sb[4*c+3];
    }
    // write this thread's h chunk + pool it
    int o = node * 8 + q * 2;
    float4 h0 = make_float4(h[q*8+0], h[q*8+1], h[q*8+2], h[q*8+3]);
    float4 h1 = make_float4(h[q*8+4], h[q*8+5], h[q*8+6], h[q*8+7]);
    reinterpret_cast<float4*>(g_h)[o]     = h0;
    reinterpret_cast<float4*>(g_h)[o + 1] = h1;
    int g = batch[node];
    atomicAdd(reinterpret_cast<float4*>(g_pooled) + g * 8 + q * 2,     h0);
    atomicAdd(reinterpret_cast<float4*>(g_pooled) + g * 8 + q * 2 + 1, h1);
    if (q == 0) atomicAdd(&g_cnt[g], 1.0f);
    // u chunk
    float acc[8];
#pragma unroll
    for (int j = 0; j < 8; j++) acc[j] = 0.f;
#pragma unroll
    for (int k = 0; k < HH; k++) {
#pragma unroll
        for (int j = 0; j < 8; j++)
            acc[j] = fmaf(h[k], sW[k * HH + q * 8 + j], acc[j]);
    }
    reinterpret_cast<float4*>(g_u)[o]     = make_float4(acc[0], acc[1], acc[2], acc[3]);
    reinterpret_cast<float4*>(g_u)[o + 1] = make_float4(acc[4], acc[5], acc[6], acc[7]);
}

// reg_output[g] = (pooled[g]/max(cnt,1)) @ Wr + br
__global__ void k_reg(const float* __restrict__ Wr, const float* __restrict__ br,
                      float* __restrict__ out) {
    int g = blockIdx.x * blockDim.x + threadIdx.x;
    if (g >= GG) return;
    float c = g_cnt[g];
    c = c < 1.f ? 1.f : c;
    float acc = 0.f;
#pragma unroll
    for (int h = 0; h < HH; h++) acc = fmaf(g_pooled[g * HH + h], Wr[h], acc);
    out[g] = acc / c + br[0];
}

// edge_pred[e] = dot(u[src_e], h[dst_e]) + bbil   (8 threads/edge, float4)
__global__ void k_edge(const int* __restrict__ asrc, const int* __restrict__ adst,
                       const float* __restrict__ bbil, float* __restrict__ out) {
    long t = (long)blockIdx.x * blockDim.x + threadIdx.x;
    int e = (int)(t >> 3), lane = (int)(t & 7);
    if (e >= EAA) return;
    float4 a = reinterpret_cast<const float4*>(g_u)[asrc[e] * 8 + lane];
    float4 b = reinterpret_cast<const float4*>(g_h)[adst[e] * 8 + lane];
    float p = a.x * b.x + a.y * b.y + a.z * b.z + a.w * b.w;
#pragma unroll
    for (int off = 4; off; off >>= 1) p += __shfl_down_sync(0xffffffffu, p, off, 8);
    if (lane == 0) out[GG + e] = p + bbil[0];
}

// ---------------- launch ----------------

extern "C" void kernel_launch(void* const* d_in, const int* in_sizes, int n_in,
                              void* d_out, int out_size) {
    const float* x    = (const float*)d_in[0];
    const int*   ei   = (const int*)  d_in[1];
    const int*   eia  = (const int*)  d_in[2];
    const int*   batch= (const int*)  d_in[3];
    const float* W1   = (const float*)d_in[4];
    const float* b1   = (const float*)d_in[5];
    const float* W2   = (const float*)d_in[6];
    const float* b2   = (const float*)d_in[7];
    const float* Wr   = (const float*)d_in[8];
    const float* br   = (const float*)d_in[9];
    const float* Wbil = (const float*)d_in[10];
    const float* bbil = (const float*)d_in[11];
    float* out = (float*)d_out;

    const int* src  = ei;
    const int* dst  = ei + EE;
    const int* asrc = eia;
    const int* adst = eia + EAA;

    const int B = 256;

    k_init  <<<(NN + B - 1) / B, B>>>();
    k_deg   <<<(EE + B - 1) / B, B>>>(dst);
    k_dinv  <<<(NN + B - 1) / B, B>>>();

    // layer 1: y1 = (x@W1)*dinv ; scatter
    k_mm1    <<<(NN * 4 + B - 1) / B, B>>>(x, W1);
    k_scatter<<<(int)(((long)EE * 8 + B - 1) / B), B>>>(src, dst);

    // fused: relu-epilogue + layer-2 matmul ; scatter
    k_layer2 <<<(NN * 4 + B - 1) / B, B>>>(b1, W2);
    k_scatter<<<(int)(((long)EE * 8 + B - 1) / B), B>>>(src, dst);

    // fused: layer-2 epilogue + pooling + u = h@Wbil
    k_head   <<<(NN * 4 + B - 1) / B, B>>>(b2, Wbil, batch);

    // heads
    k_reg    <<<(GG + B - 1) / B, B>>>(Wr, br, out);
    k_edge   <<<(int)(((long)EAA * 8 + B - 1) / B), B>>>(asrc, adst, bbil, out);
}

// round 5
// speedup vs baseline: 2.2294x; 1.3260x over previous
#include <cuda_runtime.h>

#define NN   100000
#define EE   1600000
#define EAA  1000000
#define GG   512
#define F_INN 16
#define HH   32

#define SCAN_B 1024
#define SCAN_GRID ((NN + SCAN_B - 1) / SCAN_B)

// ---- scratch (device globals) ----
__device__ __align__(16) float g_deg[NN];          // dinv
__device__ __align__(16) float g_y  [NN * HH];     // layer-1 gather source (y1)
__device__ __align__(16) float g_y2 [NN * HH];     // layer-2 gather source (y2)  [race fix]
__device__ __align__(16) float g_h  [NN * HH];     // layer-2 output (edge head)
__device__ __align__(16) float g_u  [NN * HH];     // h @ Wbil
__device__ __align__(16) float g_pooled[GG * HH];
__device__ float g_cnt[GG];
__device__ int   g_cnt_i[NN];                      // in-degree (no self loop)
__device__ int   g_pos[NN];                        // CSR row start
__device__ int   g_cur[NN];                        // fill cursors
__device__ int   g_csr[EE];                        // src ids grouped by dst
__device__ int   g_total;

// ---------------- build kernels ----------------

__global__ void k_zero() {
    int i = blockIdx.x * blockDim.x + threadIdx.x;
    if (i < NN) { g_cnt_i[i] = 0; g_cur[i] = 0; }
    if (i < GG * HH) g_pooled[i] = 0.f;
    if (i < GG)      g_cnt[i] = 0.f;
    if (i == 0)      g_total = 0;
}

__global__ void k_count(const int* __restrict__ dst) {
    int e = blockIdx.x * blockDim.x + threadIdx.x;
    if (e < EE) atomicAdd(&g_cnt_i[dst[e]], 1);
}

// blockwise exclusive scan; block base via one atomicAdd per block.
// also computes dinv = rsqrt(deg+1).
__global__ void k_scan() {
    __shared__ int s[SCAN_B];
    __shared__ int base;
    int tid = threadIdx.x;
    int i = blockIdx.x * SCAN_B + tid;
    int v = (i < NN) ? g_cnt_i[i] : 0;
    s[tid] = v;
    __syncthreads();
#pragma unroll
    for (int off = 1; off < SCAN_B; off <<= 1) {
        int t = (tid >= off) ? s[tid - off] : 0;
        __syncthreads();
        s[tid] += t;
        __syncthreads();
    }
    if (tid == 0) base = atomicAdd(&g_total, s[SCAN_B - 1]);
    __syncthreads();
    if (i < NN) {
        g_pos[i] = base + s[tid] - v;          // exclusive
        g_deg[i] = rsqrtf((float)v + 1.0f);    // dinv incl self-loop
    }
}

__global__ void k_fill(const int* __restrict__ src, const int* __restrict__ dst) {
    int e = blockIdx.x * blockDim.x + threadIdx.x;
    if (e >= EE) return;
    int d = dst[e];
    int slot = atomicAdd(&g_cur[d], 1);
    g_csr[g_pos[d] + slot] = src[e];
}

// ---------------- compute kernels ----------------

// y1 = (x @ W1) * dinv ; 4 threads per node
__global__ void k_mm1(const float* __restrict__ x, const float* __restrict__ W1) {
    __shared__ float sW[F_INN * HH];
    for (int i = threadIdx.x; i < F_INN * HH; i += blockDim.x) sW[i] = W1[i];
    __syncthreads();
    int t = blockIdx.x * blockDim.x + threadIdx.x;
    int node = t >> 2, q = t & 3;
    if (node >= NN) return;
    float acc[8];
#pragma unroll
    for (int j = 0; j < 8; j++) acc[j] = 0.f;
    const float4* xr = reinterpret_cast<const float4*>(x + node * F_INN);
#pragma unroll
    for (int kk = 0; kk < F_INN / 4; kk++) {
        float4 xv = xr[kk];
        float xs[4] = {xv.x, xv.y, xv.z, xv.w};
#pragma unroll
        for (int p = 0; p < 4; p++) {
            int k = kk * 4 + p;
#pragma unroll
            for (int j = 0; j < 8; j++)
                acc[j] = fmaf(xs[p], sW[k * HH + q * 8 + j], acc[j]);
        }
    }
    float dv = g_deg[node];
    int o = node * 8 + q * 2;
    reinterpret_cast<float4*>(g_y)[o]     = make_float4(acc[0]*dv, acc[1]*dv, acc[2]*dv, acc[3]*dv);
    reinterpret_cast<float4*>(g_y)[o + 1] = make_float4(acc[4]*dv, acc[5]*dv, acc[6]*dv, acc[7]*dv);
}

// fused: CSR gather of y1 + relu epilogue (smem) + @W2 matmul -> y2 (*dinv)
// block = 256 threads = 32 nodes x 8 chunks. Writes g_y2 (NOT g_y: race-free).
#define NODES_PER_BLK 32
#define HPAD 36
__global__ void k_gmm(const float* __restrict__ b1, const float* __restrict__ W2) {
    __shared__ float sW[HH * HH];
    __shared__ float sb[HH];
    __shared__ float sh[NODES_PER_BLK * HPAD];
    for (int i = threadIdx.x; i < HH * HH; i += blockDim.x) sW[i] = W2[i];
    if (threadIdx.x < HH) sb[threadIdx.x] = b1[threadIdx.x];
    __syncthreads();

    int tid = threadIdx.x;
    int nl = tid >> 3, c = tid & 7;              // local node, float4 chunk
    int node = blockIdx.x * NODES_PER_BLK + nl;
    bool ok = node < NN;

    if (ok) {
        int base = g_pos[node];
        int m    = g_cnt_i[node];
        const float4* y4 = reinterpret_cast<const float4*>(g_y);
        float4 acc = y4[node * 8 + c];           // self-loop term
        int i = 0;
        for (; i + 2 <= m; i += 2) {
            int s0 = g_csr[base + i];
            int s1 = g_csr[base + i + 1];
            float4 v0 = y4[s0 * 8 + c];
            float4 v1 = y4[s1 * 8 + c];
            acc.x += v0.x + v1.x; acc.y += v0.y + v1.y;
            acc.z += v0.z + v1.z; acc.w += v0.w + v1.w;
        }
        if (i < m) {
            float4 v = y4[g_csr[base + i] * 8 + c];
            acc.x += v.x; acc.y += v.y; acc.z += v.z; acc.w += v.w;
        }
        float dv = g_deg[node];
        float* hr = sh + nl * HPAD + c * 4;
        hr[0] = fmaxf(acc.x * dv + sb[c*4+0], 0.f);
        hr[1] = fmaxf(acc.y * dv + sb[c*4+1], 0.f);
        hr[2] = fmaxf(acc.z * dv + sb[c*4+2], 0.f);
        hr[3] = fmaxf(acc.w * dv + sb[c*4+3], 0.f);
    }
    __syncthreads();
    if (!ok) return;

    float a0 = 0.f, a1 = 0.f, a2 = 0.f, a3 = 0.f;
    const float* hrow = sh + nl * HPAD;
#pragma unroll
    for (int k = 0; k < HH; k++) {
        float hv = hrow[k];
        a0 = fmaf(hv, sW[k * HH + c * 4 + 0], a0);
        a1 = fmaf(hv, sW[k * HH + c * 4 + 1], a1);
        a2 = fmaf(hv, sW[k * HH + c * 4 + 2], a2);
        a3 = fmaf(hv, sW[k * HH + c * 4 + 3], a3);
    }
    float dv = g_deg[node];
    reinterpret_cast<float4*>(g_y2)[node * 8 + c] =
        make_float4(a0 * dv, a1 * dv, a2 * dv, a3 * dv);
}

// fused: CSR gather of y2 + epilogue -> g_h, pooling, u = h2 @ Wbil -> g_u
__global__ void k_ghead(const float* __restrict__ b2, const float* __restrict__ Wbil,
                        const int* __restrict__ batch) {
    __shared__ float sW[HH * HH];
    __shared__ float sb[HH];
    __shared__ float sh[NODES_PER_BLK * HPAD];
    for (int i = threadIdx.x; i < HH * HH; i += blockDim.x) sW[i] = Wbil[i];
    if (threadIdx.x < HH) sb[threadIdx.x] = b2[threadIdx.x];
    __syncthreads();

    int tid = threadIdx.x;
    int nl = tid >> 3, c = tid & 7;
    int node = blockIdx.x * NODES_PER_BLK + nl;
    bool ok = node < NN;

    if (ok) {
        int base = g_pos[node];
        int m    = g_cnt_i[node];
        const float4* y4 = reinterpret_cast<const float4*>(g_y2);
        float4 acc = y4[node * 8 + c];
        int i = 0;
        for (; i + 2 <= m; i += 2) {
            int s0 = g_csr[base + i];
            int s1 = g_csr[base + i + 1];
            float4 v0 = y4[s0 * 8 + c];
            float4 v1 = y4[s1 * 8 + c];
            acc.x += v0.x + v1.x; acc.y += v0.y + v1.y;
            acc.z += v0.z + v1.z; acc.w += v0.w + v1.w;
        }
        if (i < m) {
            float4 v = y4[g_csr[base + i] * 8 + c];
            acc.x += v.x; acc.y += v.y; acc.z += v.z; acc.w += v.w;
        }
        float dv = g_deg[node];
        float4 h2;
        h2.x = acc.x * dv + sb[c*4+0];
        h2.y = acc.y * dv + sb[c*4+1];
        h2.z = acc.z * dv + sb[c*4+2];
        h2.w = acc.w * dv + sb[c*4+3];
        float* hr = sh + nl * HPAD + c * 4;
        hr[0] = h2.x; hr[1] = h2.y; hr[2] = h2.z; hr[3] = h2.w;
        reinterpret_cast<float4*>(g_h)[node * 8 + c] = h2;
        int g = batch[node];
        atomicAdd(reinterpret_cast<float4*>(g_pooled) + g * 8 + c, h2);
        if (c == 0) atomicAdd(&g_cnt[g], 1.0f);
    }
    __syncthreads();
    if (!ok) return;

    float a0 = 0.f, a1 = 0.f, a2 = 0.f, a3 = 0.f;
    const float* hrow = sh + nl * HPAD;
#pragma unroll
    for (int k = 0; k < HH; k++) {
        float hv = hrow[k];
        a0 = fmaf(hv, sW[k * HH + c * 4 + 0], a0);
        a1 = fmaf(hv, sW[k * HH + c * 4 + 1], a1);
        a2 = fmaf(hv, sW[k * HH + c * 4 + 2], a2);
        a3 = fmaf(hv, sW[k * HH + c * 4 + 3], a3);
    }
    reinterpret_cast<float4*>(g_u)[node * 8 + c] = make_float4(a0, a1, a2, a3);
}

// reg_output[g] = (pooled[g]/max(cnt,1)) @ Wr + br
__global__ void k_reg(const float* __restrict__ Wr, const float* __restrict__ br,
                      float* __restrict__ out) {
    int g = blockIdx.x * blockDim.x + threadIdx.x;
    if (g >= GG) return;
    float c = g_cnt[g];
    c = c < 1.f ? 1.f : c;
    float acc = 0.f;
#pragma unroll
    for (int h = 0; h < HH; h++) acc = fmaf(g_pooled[g * HH + h], Wr[h], acc);
    out[g] = acc / c + br[0];
}

// edge_pred[e] = dot(u[src_e], h[dst_e]) + bbil   (8 threads/edge, float4)
__global__ void k_edge(const int* __restrict__ asrc, const int* __restrict__ adst,
                       const float* __restrict__ bbil, float* __restrict__ out) {
    long t = (long)blockIdx.x * blockDim.x + threadIdx.x;
    int e = (int)(t >> 3), lane = (int)(t & 7);
    if (e >= EAA) return;
    float4 a = reinterpret_cast<const float4*>(g_u)[asrc[e] * 8 + lane];
    float4 b = reinterpret_cast<const float4*>(g_h)[adst[e] * 8 + lane];
    float p = a.x * b.x + a.y * b.y + a.z * b.z + a.w * b.w;
#pragma unroll
    for (int off = 4; off; off >>= 1) p += __shfl_down_sync(0xffffffffu, p, off, 8);
    if (lane == 0) out[GG + e] = p + bbil[0];
}

// ---------------- launch ----------------

extern "C" void kernel_launch(void* const* d_in, const int* in_sizes, int n_in,
                              void* d_out, int out_size) {
    const float* x    = (const float*)d_in[0];
    const int*   ei   = (const int*)  d_in[1];
    const int*   eia  = (const int*)  d_in[2];
    const int*   batch= (const int*)  d_in[3];
    const float* W1   = (const float*)d_in[4];
    const float* b1   = (const float*)d_in[5];
    const float* W2   = (const float*)d_in[6];
    const float* b2   = (const float*)d_in[7];
    const float* Wr   = (const float*)d_in[8];
    const float* br   = (const float*)d_in[9];
    const float* Wbil = (const float*)d_in[10];
    const float* bbil = (const float*)d_in[11];
    float* out = (float*)d_out;

    const int* src  = ei;
    const int* dst  = ei + EE;
    const int* asrc = eia;
    const int* adst = eia + EAA;

    const int B = 256;

    // CSR build
    k_zero <<<(NN + B - 1) / B, B>>>();
    k_count<<<(EE + B - 1) / B, B>>>(dst);
    k_scan <<<SCAN_GRID, SCAN_B>>>();
    k_fill <<<(EE + B - 1) / B, B>>>(src, dst);

    // layer 1 matmul, then fused gather+relu+layer2 matmul (y1 -> y2)
    k_mm1  <<<(NN * 4 + B - 1) / B, B>>>(x, W1);
    k_gmm  <<<(NN + NODES_PER_BLK - 1) / NODES_PER_BLK, B>>>(b1, W2);

    // fused gather(y2) + epilogue + pooling + bilinear precompute
    k_ghead<<<(NN + NODES_PER_BLK - 1) / NODES_PER_BLK, B>>>(b2, Wbil, batch);

    // heads
    k_reg  <<<(GG + B - 1) / B, B>>>(Wr, br, out);
    k_edge <<<(int)(((long)EAA * 8 + B - 1) / B), B>>>(asrc, adst, bbil, out);
}